// round 16
// baseline (speedup 1.0000x reference)
#include <cuda_runtime.h>
#include <utility>
#include <math.h>

// ============================================================================
// Compile-time real-basis Wigner 3j (Clebsch-Gordan) coefficients.
// ============================================================================
namespace cgc {

__host__ __device__ constexpr double cfact(int n) {
  double r = 1.0;
  for (int i = 2; i <= n; ++i) r *= (double)i;
  return r;
}
__host__ __device__ constexpr double psign(int k) {
  return (k % 2 == 0) ? 1.0 : -1.0;
}
__host__ __device__ constexpr double csqrt(double x) {
  if (x <= 0.0) return 0.0;
  double r = x >= 1.0 ? x : 1.0;
  for (int i = 0; i < 200; ++i) {
    double nr = 0.5 * (r + x / r);
    if (nr == r) break;
    r = nr;
  }
  return r;
}

__host__ __device__ constexpr double w3jc(int l1, int l2, int l3, int m1,
                                          int m2) {
  const int m3 = -m1 - m2;
  if (m3 < -l3 || m3 > l3) return 0.0;
  const double tri = cfact(l1 + l2 - l3) * cfact(l1 - l2 + l3) *
                     cfact(-l1 + l2 + l3) / cfact(l1 + l2 + l3 + 1);
  const double pref =
      psign(l1 - l2 - m3) *
      csqrt(tri * cfact(l1 + m1) * cfact(l1 - m1) * cfact(l2 + m2) *
            cfact(l2 - m2) * cfact(l3 + m3) * cfact(l3 - m3));
  int t0 = 0;
  if (l2 - l3 - m1 > t0) t0 = l2 - l3 - m1;
  if (l1 - l3 + m2 > t0) t0 = l1 - l3 + m2;
  int t1 = l1 + l2 - l3;
  if (l1 - m1 < t1) t1 = l1 - m1;
  if (l2 + m2 < t1) t1 = l2 + m2;
  double s = 0.0;
  for (int t = t0; t <= t1; ++t) {
    s += psign(t) / (cfact(t) * cfact(l1 + l2 - l3 - t) * cfact(l1 - m1 - t) *
                     cfact(l2 + m2 - t) * cfact(l3 - l2 + m1 + t) *
                     cfact(l3 - l1 - m2 + t));
  }
  return pref * s;
}

struct URow {
  int n;
  int col[2];
  double re[2];
  double im[2];
};

__host__ __device__ constexpr URow urow(int l, int i) {
  URow r{};
  const double s2 = csqrt(0.5);
  const int mu = i - l;
  if (mu == 0) {
    r.n = 1;
    r.col[0] = l; r.re[0] = 1.0; r.im[0] = 0.0;
  } else if (mu > 0) {
    r.n = 2;
    r.col[0] = l + mu; r.re[0] = psign(mu) * s2; r.im[0] = 0.0;
    r.col[1] = l - mu; r.re[1] = s2;             r.im[1] = 0.0;
  } else {
    const int m = -mu;
    r.n = 2;
    r.col[0] = l - m; r.re[0] = 0.0; r.im[0] = s2;
    r.col[1] = l + m; r.re[1] = 0.0; r.im[1] = -psign(m) * s2;
  }
  return r;
}

__host__ __device__ constexpr double cg_real(int l1, int l2, int l3, int i,
                                             int j, int k) {
  const URow r1 = urow(l1, i);
  const URow r2 = urow(l2, j);
  const URow r3 = urow(l3, k);
  double acc = 0.0;
  for (int a = 0; a < r1.n; ++a)
    for (int b = 0; b < r2.n; ++b) {
      const int m1 = r1.col[a] - l1;
      const int m2 = r2.col[b] - l2;
      const int m3 = -m1 - m2;
      if (m3 < -l3 || m3 > l3) continue;
      const int cidx = m3 + l3;
      for (int c = 0; c < r3.n; ++c) {
        if (r3.col[c] != cidx) continue;
        const double re12 = r1.re[a] * r2.re[b] - r1.im[a] * r2.im[b];
        const double im12 = r1.re[a] * r2.im[b] + r1.im[a] * r2.re[b];
        const double rp = re12 * r3.re[c] - im12 * r3.im[c];
        if (rp != 0.0) acc += rp * w3jc(l1, l2, l3, m1, m2);
      }
    }
  return acc;
}

}  // namespace cgc

// ============================================================================
// Fully-unrolled tensor-product component (FFMA-immediate, zeros elided).
// ============================================================================
template <int L1, int L2, int LO, int K, int I, int J>
__device__ __forceinline__ void add_term(float& a0, float& a1,
                                         const float* __restrict__ x,
                                         const float* __restrict__ y) {
  constexpr float c = (float)cgc::cg_real(L1, L2, LO, I, J, K);
  if constexpr (c > 1e-7f || c < -1e-7f) {
    if constexpr (((I + J) & 1) == 0)
      a0 += c * (x[I] * y[J]);
    else
      a1 += c * (x[I] * y[J]);
  }
}

template <int L1, int L2, int LO, int K, int I, int... Js>
__device__ __forceinline__ void add_row(float& a0, float& a1, const float* x,
                                        const float* y,
                                        std::integer_sequence<int, Js...>) {
  (add_term<L1, L2, LO, K, I, Js>(a0, a1, x, y), ...);
}

template <int L1, int L2, int LO, int K, int... Is>
__device__ __forceinline__ void add_all(float& a0, float& a1, const float* x,
                                        const float* y,
                                        std::integer_sequence<int, Is...>) {
  (add_row<L1, L2, LO, K, Is>(a0, a1, x, y,
                              std::make_integer_sequence<int, 2 * L2 + 1>{}),
   ...);
}

template <int L1, int L2, int LO, int K>
__device__ __forceinline__ float tp_k(const float* x, const float* y) {
  float a0 = 0.f, a1 = 0.f;
  add_all<L1, L2, LO, K>(a0, a1, x, y,
                         std::make_integer_sequence<int, 2 * L1 + 1>{});
  return a0 + a1;
}

// ============================================================================
// Kernel constants / layout
// ============================================================================
constexpr int TILE = 128;
constexpr int NPX = TILE + 2;   // 130 halo pixels per row
constexpr int SSTR = 129;       // staging stride (odd -> conflict-free)
constexpr int F6OFF = 3 * NPX * 9;  // general path: f6 plane offset (3510)
constexpr int POOLN = 88 * SSTR;    // 11352 floats = 45408 B (max of all uses)
// fast (uniform-weight) layout inside pool:
constexpr int VS4 = 0;                  // vertical sums, f4: NPX*9
constexpr int C4 = NPX * 9;             // center row, f4:   NPX*9
constexpr int VS6 = 2 * NPX * 9;        // vertical sums, f6: NPX*13
constexpr int C6 = 2 * NPX * 9 + NPX * 13;  // center row, f6

// compile-time residual selector for output column col (0..87)
template <int COL>
__device__ __forceinline__ float res_of(const float* __restrict__ x) {
  if constexpr (COL < 36)
    return x[COL % 9];
  else
    return x[9 + (COL - 36) % 13];
}

// fold one lo=4 component K4: 4 path t-values -> 4 copies -> staging
template <int K4>
__device__ __forceinline__ void fold4(float* __restrict__ pool, int tid,
                                      const float* __restrict__ x,
                                      const float* __restrict__ y,
                                      const float* __restrict__ w4) {
  const float t0 = tp_k<4, 4, 4, K4>(x, y);
  const float t1 = tp_k<4, 6, 4, K4>(x, y + 9);
  const float t2 = tp_k<6, 4, 4, K4>(x + 9, y);
  const float t3 = tp_k<6, 6, 4, K4>(x + 9, y + 9);
#pragma unroll
  for (int c = 0; c < 4; ++c) {
    float v = w4[c * 4 + 0] * t0 + w4[c * 4 + 1] * t1 + w4[c * 4 + 2] * t2 +
              w4[c * 4 + 3] * t3;
    if (c == 0) v += res_of<K4 + 0 * 22>(x);
    if (c == 1) v += res_of<K4 + 1 * 22>(x);
    if (c == 2) v += res_of<K4 + 2 * 22>(x);
    if (c == 3) v += res_of<K4 + 3 * 22>(x);
    pool[(c * 22 + K4) * SSTR + tid] = v;
  }
}

// fold one lo=6 component K6
template <int K6>
__device__ __forceinline__ void fold6(float* __restrict__ pool, int tid,
                                      const float* __restrict__ x,
                                      const float* __restrict__ y,
                                      const float* __restrict__ w6) {
  const float s0 = tp_k<4, 4, 6, K6>(x, y);
  const float s1 = tp_k<4, 6, 6, K6>(x, y + 9);
  const float s2 = tp_k<6, 4, 6, K6>(x + 9, y);
  const float s3 = tp_k<6, 6, 6, K6>(x + 9, y + 9);
#pragma unroll
  for (int c = 0; c < 4; ++c) {
    float v = w6[c * 4 + 0] * s0 + w6[c * 4 + 1] * s1 + w6[c * 4 + 2] * s2 +
              w6[c * 4 + 3] * s3;
    if (c == 0) v += res_of<9 + K6 + 0 * 22>(x);
    if (c == 1) v += res_of<9 + K6 + 1 * 22>(x);
    if (c == 2) v += res_of<9 + K6 + 2 * 22>(x);
    if (c == 3) v += res_of<9 + K6 + 3 * 22>(x);
    pool[(c * 22 + 9 + K6) * SSTR + tid] = v;
  }
}

// one |m| group: +m and -m of lo=4 and lo=6 share products -> one scope
template <int M>
__device__ __forceinline__ void emit_m(float* pool, int tid, const float* x,
                                       const float* y, const float* w4,
                                       const float* w6) {
  if constexpr (M <= 4) {
    fold4<4 + M>(pool, tid, x, y, w4);
    if constexpr (M > 0) fold4<4 - M>(pool, tid, x, y, w4);
  }
  fold6<6 + M>(pool, tid, x, y, w6);
  if constexpr (M > 0) fold6<6 - M>(pool, tid, x, y, w6);
}

template <int... Ms>
__device__ __forceinline__ void emit_all(float* pool, int tid, const float* x,
                                         const float* y, const float* w4,
                                         const float* w6,
                                         std::integer_sequence<int, Ms...>) {
  (emit_m<Ms>(pool, tid, x, y, w4, w6), ...);
}

// ============================================================================
// Main kernel
// ============================================================================
__global__ __launch_bounds__(TILE, 4) void esc_kernel(
    const float* __restrict__ f4, const float* __restrict__ f6,
    const float* __restrict__ sw, const float* __restrict__ tw,
    float* __restrict__ out, int H, int W) {
  __shared__ float pool[POOLN];

  const int tid = threadIdx.x;
  const int h = blockIdx.y;
  const int w0 = blockIdx.x * TILE;
  const bool valid = (w0 + tid) < W;

  float s9[9];
#pragma unroll
  for (int i = 0; i < 9; ++i) s9[i] = __ldg(sw + i);
  bool uniform = true;
#pragma unroll
  for (int i = 1; i < 9; ++i) uniform = uniform && (s9[i] == s9[0]);

  int gh0 = h - 1 < 0 ? 0 : h - 1;
  int gh2 = h + 1 >= H ? H - 1 : h + 1;
  const bool xinterior = (w0 - 1 >= 0) && (w0 - 1 + NPX <= W);

  // ---- phase A: stage conv inputs into smem
  if (uniform) {
    // fast layout: vertical-sum plane + center-row plane (per irrep)
    if (xinterior) {
      const long b0 = ((long)gh0 * W + w0 - 1);
      const long b1 = ((long)h * W + w0 - 1);
      const long b2 = ((long)gh2 * W + w0 - 1);
      const float* r40 = f4 + b0 * 9;
      const float* r41 = f4 + b1 * 9;
      const float* r42 = f4 + b2 * 9;
      for (int i = tid; i < NPX * 9; i += TILE) {
        float a = __ldg(r40 + i), b = __ldg(r41 + i), c = __ldg(r42 + i);
        pool[VS4 + i] = a + b + c;
        pool[C4 + i] = b;
      }
      const float* r60 = f6 + b0 * 13;
      const float* r61 = f6 + b1 * 13;
      const float* r62 = f6 + b2 * 13;
      for (int i = tid; i < NPX * 13; i += TILE) {
        float a = __ldg(r60 + i), b = __ldg(r61 + i), c = __ldg(r62 + i);
        pool[VS6 + i] = a + b + c;
        pool[C6 + i] = b;
      }
    } else {
      for (int px = tid; px < NPX; px += TILE) {
        int gw = w0 - 1 + px;
        gw = gw < 0 ? 0 : (gw >= W ? W - 1 : gw);
        const float* p0 = f4 + ((long)gh0 * W + gw) * 9;
        const float* p1 = f4 + ((long)h * W + gw) * 9;
        const float* p2 = f4 + ((long)gh2 * W + gw) * 9;
#pragma unroll
        for (int c = 0; c < 9; ++c) {
          float a = __ldg(p0 + c), b = __ldg(p1 + c), d = __ldg(p2 + c);
          pool[VS4 + px * 9 + c] = a + b + d;
          pool[C4 + px * 9 + c] = b;
        }
        const float* q0 = f6 + ((long)gh0 * W + gw) * 13;
        const float* q1 = f6 + ((long)h * W + gw) * 13;
        const float* q2 = f6 + ((long)gh2 * W + gw) * 13;
#pragma unroll
        for (int c = 0; c < 13; ++c) {
          float a = __ldg(q0 + c), b = __ldg(q1 + c), d = __ldg(q2 + c);
          pool[VS6 + px * 13 + c] = a + b + d;
          pool[C6 + px * 13 + c] = b;
        }
      }
    }
  } else {
    // general layout: 3 full rows per irrep (packed like global)
    for (int px = tid; px < NPX; px += TILE) {
      int gw = w0 - 1 + px;
      gw = gw < 0 ? 0 : (gw >= W ? W - 1 : gw);
#pragma unroll
      for (int r = 0; r < 3; ++r) {
        int gh = h - 1 + r;
        gh = gh < 0 ? 0 : (gh >= H ? H - 1 : gh);
        const long nn = (long)gh * W + gw;
        const float* s4 = f4 + nn * 9;
        float* d4 = pool + r * (NPX * 9) + px * 9;
#pragma unroll
        for (int c = 0; c < 9; ++c) d4[c] = __ldg(s4 + c);
        const float* s6 = f6 + nn * 13;
        float* d6 = pool + F6OFF + r * (NPX * 13) + px * 13;
#pragma unroll
        for (int c = 0; c < 13; ++c) d6[c] = __ldg(s6 + c);
      }
    }
  }
  __syncthreads();

  // ---- phase B1: 3x3 conv -> x[22], y[22]
  float x[22], y[22];
  if (valid) {
    if (uniform) {
      const float wu = s9[0];
#pragma unroll
      for (int ch = 0; ch < 9; ++ch) {
        y[ch] = wu * (pool[VS4 + (tid + 0) * 9 + ch] +
                      pool[VS4 + (tid + 1) * 9 + ch] +
                      pool[VS4 + (tid + 2) * 9 + ch]);
        x[ch] = pool[C4 + (tid + 1) * 9 + ch];
      }
#pragma unroll
      for (int ch = 0; ch < 13; ++ch) {
        y[9 + ch] = wu * (pool[VS6 + (tid + 0) * 13 + ch] +
                          pool[VS6 + (tid + 1) * 13 + ch] +
                          pool[VS6 + (tid + 2) * 13 + ch]);
        x[9 + ch] = pool[C6 + (tid + 1) * 13 + ch];
      }
    } else {
#pragma unroll
      for (int ch = 0; ch < 9; ++ch) {
        float a = 0.f;
#pragma unroll
        for (int dr = 0; dr < 3; ++dr)
#pragma unroll
          for (int dc = 0; dc < 3; ++dc)
            a += s9[dr * 3 + dc] * pool[dr * (NPX * 9) + (tid + dc) * 9 + ch];
        y[ch] = a;
        x[ch] = pool[1 * (NPX * 9) + (tid + 1) * 9 + ch];
      }
#pragma unroll
      for (int ch = 0; ch < 13; ++ch) {
        float a = 0.f;
#pragma unroll
        for (int dr = 0; dr < 3; ++dr)
#pragma unroll
          for (int dc = 0; dc < 3; ++dc)
            a += s9[dr * 3 + dc] *
                 pool[F6OFF + dr * (NPX * 13) + (tid + dc) * 13 + ch];
        y[9 + ch] = a;
        x[9 + ch] = pool[F6OFF + 1 * (NPX * 13) + (tid + 1) * 13 + ch];
      }
    }
  }
  __syncthreads();  // conv tiles dead; pool becomes staging

  // ---- phase B2: streamed tensor products, grouped by |m|
  if (valid) {
    const float A4 = 1.5f;                 // sqrt(9/4)
    const float A6 = 1.8027756377319946f;  // sqrt(13/4)
    float w4[16], w6[16];
#pragma unroll
    for (int c = 0; c < 4; ++c)
#pragma unroll
      for (int p = 0; p < 4; ++p) {
        w4[c * 4 + p] = A4 * __ldg(tw + c * 8 + p);
        w6[c * 4 + p] = A6 * __ldg(tw + c * 8 + 4 + p);
      }

    emit_all(pool, tid, x, y, w4, w6, std::make_integer_sequence<int, 7>{});
  }
  __syncthreads();

  // ---- phase C: cooperative coalesced float4 stores
  const long rowbase = (long)h * W;
#pragma unroll
  for (int it = 0; it < 9; ++it) {
    int e = it * TILE + tid;
    int px = e / 9;
    int g = e - px * 9;
    int wp = w0 + px;
    if (wp < W) {
      int s = g * 4;
      float4 v =
          make_float4(pool[(s + 0) * SSTR + px], pool[(s + 1) * SSTR + px],
                      pool[(s + 2) * SSTR + px], pool[(s + 3) * SSTR + px]);
      *reinterpret_cast<float4*>(out + (rowbase + wp) * 36 + s) = v;
    }
  }
  float* out2 = out + (long)H * W * 36;
#pragma unroll
  for (int it = 0; it < 13; ++it) {
    int e = it * TILE + tid;
    int px = e / 13;
    int g = e - px * 13;
    int wp = w0 + px;
    if (wp < W) {
      int s = 36 + g * 4;
      float4 v =
          make_float4(pool[(s + 0) * SSTR + px], pool[(s + 1) * SSTR + px],
                      pool[(s + 2) * SSTR + px], pool[(s + 3) * SSTR + px]);
      *reinterpret_cast<float4*>(out2 + (rowbase + wp) * 52 + g * 4) = v;
    }
  }
}

// ============================================================================
extern "C" void kernel_launch(void* const* d_in, const int* in_sizes, int n_in,
                              void* d_out, int out_size) {
  (void)n_in;
  (void)out_size;
  const float* f4 = (const float*)d_in[0];
  const float* f6 = (const float*)d_in[1];
  const float* sw = (const float*)d_in[2];
  const float* tw = (const float*)d_in[3];
  float* out = (float*)d_out;

  const long n = (long)in_sizes[0] / 9;  // HW
  int W = (int)(sqrt((double)n) + 0.5);  // H = W = 768 here
  if (W < 1) W = 1;
  int H = (int)(n / W);

  dim3 grid((W + TILE - 1) / TILE, H);
  esc_kernel<<<grid, TILE>>>(f4, f6, sw, tw, out, H, W);
}

// round 17
// speedup vs baseline: 1.3360x; 1.3360x over previous
#include <cuda_runtime.h>
#include <utility>
#include <math.h>

// ============================================================================
// Compile-time real-basis Wigner 3j (Clebsch-Gordan) coefficients.
// ============================================================================
namespace cgc {

__host__ __device__ constexpr double cfact(int n) {
  double r = 1.0;
  for (int i = 2; i <= n; ++i) r *= (double)i;
  return r;
}
__host__ __device__ constexpr double psign(int k) {
  return (k % 2 == 0) ? 1.0 : -1.0;
}
__host__ __device__ constexpr double csqrt(double x) {
  if (x <= 0.0) return 0.0;
  double r = x >= 1.0 ? x : 1.0;
  for (int i = 0; i < 200; ++i) {
    double nr = 0.5 * (r + x / r);
    if (nr == r) break;
    r = nr;
  }
  return r;
}

__host__ __device__ constexpr double w3jc(int l1, int l2, int l3, int m1,
                                          int m2) {
  const int m3 = -m1 - m2;
  if (m3 < -l3 || m3 > l3) return 0.0;
  const double tri = cfact(l1 + l2 - l3) * cfact(l1 - l2 + l3) *
                     cfact(-l1 + l2 + l3) / cfact(l1 + l2 + l3 + 1);
  const double pref =
      psign(l1 - l2 - m3) *
      csqrt(tri * cfact(l1 + m1) * cfact(l1 - m1) * cfact(l2 + m2) *
            cfact(l2 - m2) * cfact(l3 + m3) * cfact(l3 - m3));
  int t0 = 0;
  if (l2 - l3 - m1 > t0) t0 = l2 - l3 - m1;
  if (l1 - l3 + m2 > t0) t0 = l1 - l3 + m2;
  int t1 = l1 + l2 - l3;
  if (l1 - m1 < t1) t1 = l1 - m1;
  if (l2 + m2 < t1) t1 = l2 + m2;
  double s = 0.0;
  for (int t = t0; t <= t1; ++t) {
    s += psign(t) / (cfact(t) * cfact(l1 + l2 - l3 - t) * cfact(l1 - m1 - t) *
                     cfact(l2 + m2 - t) * cfact(l3 - l2 + m1 + t) *
                     cfact(l3 - l1 - m2 + t));
  }
  return pref * s;
}

struct URow {
  int n;
  int col[2];
  double re[2];
  double im[2];
};

__host__ __device__ constexpr URow urow(int l, int i) {
  URow r{};
  const double s2 = csqrt(0.5);
  const int mu = i - l;
  if (mu == 0) {
    r.n = 1;
    r.col[0] = l; r.re[0] = 1.0; r.im[0] = 0.0;
  } else if (mu > 0) {
    r.n = 2;
    r.col[0] = l + mu; r.re[0] = psign(mu) * s2; r.im[0] = 0.0;
    r.col[1] = l - mu; r.re[1] = s2;             r.im[1] = 0.0;
  } else {
    const int m = -mu;
    r.n = 2;
    r.col[0] = l - m; r.re[0] = 0.0; r.im[0] = s2;
    r.col[1] = l + m; r.re[1] = 0.0; r.im[1] = -psign(m) * s2;
  }
  return r;
}

__host__ __device__ constexpr double cg_real(int l1, int l2, int l3, int i,
                                             int j, int k) {
  const URow r1 = urow(l1, i);
  const URow r2 = urow(l2, j);
  const URow r3 = urow(l3, k);
  double acc = 0.0;
  for (int a = 0; a < r1.n; ++a)
    for (int b = 0; b < r2.n; ++b) {
      const int m1 = r1.col[a] - l1;
      const int m2 = r2.col[b] - l2;
      const int m3 = -m1 - m2;
      if (m3 < -l3 || m3 > l3) continue;
      const int cidx = m3 + l3;
      for (int c = 0; c < r3.n; ++c) {
        if (r3.col[c] != cidx) continue;
        const double re12 = r1.re[a] * r2.re[b] - r1.im[a] * r2.im[b];
        const double im12 = r1.re[a] * r2.im[b] + r1.im[a] * r2.re[b];
        const double rp = re12 * r3.re[c] - im12 * r3.im[c];
        if (rp != 0.0) acc += rp * w3jc(l1, l2, l3, m1, m2);
      }
    }
  return acc;
}

}  // namespace cgc

// ============================================================================
// Fully-unrolled tensor-product component (FFMA-immediate, zeros elided).
// ============================================================================
template <int L1, int L2, int LO, int K, int I, int J>
__device__ __forceinline__ void add_term(float& a0, float& a1,
                                         const float* __restrict__ x,
                                         const float* __restrict__ y) {
  constexpr float c = (float)cgc::cg_real(L1, L2, LO, I, J, K);
  if constexpr (c > 1e-7f || c < -1e-7f) {
    if constexpr (((I + J) & 1) == 0)
      a0 += c * (x[I] * y[J]);
    else
      a1 += c * (x[I] * y[J]);
  }
}

template <int L1, int L2, int LO, int K, int I, int... Js>
__device__ __forceinline__ void add_row(float& a0, float& a1, const float* x,
                                        const float* y,
                                        std::integer_sequence<int, Js...>) {
  (add_term<L1, L2, LO, K, I, Js>(a0, a1, x, y), ...);
}

template <int L1, int L2, int LO, int K, int... Is>
__device__ __forceinline__ void add_all(float& a0, float& a1, const float* x,
                                        const float* y,
                                        std::integer_sequence<int, Is...>) {
  (add_row<L1, L2, LO, K, Is>(a0, a1, x, y,
                              std::make_integer_sequence<int, 2 * L2 + 1>{}),
   ...);
}

template <int L1, int L2, int LO, int K>
__device__ __forceinline__ float tp_k(const float* x, const float* y) {
  float a0 = 0.f, a1 = 0.f;
  add_all<L1, L2, LO, K>(a0, a1, x, y,
                         std::make_integer_sequence<int, 2 * L1 + 1>{});
  return a0 + a1;
}

// ============================================================================
// Kernel constants / layout
// ============================================================================
constexpr int TILE = 128;
constexpr int NPX = TILE + 2;       // 130 halo pixels per row
constexpr int SSTR = 129;           // staging stride (odd -> conflict-free)
constexpr int F6OFF = 3 * NPX * 9;  // f6 plane offset (3510)
constexpr int POOLN = 88 * SSTR;    // 11352 floats = 45408 B

// compile-time residual selector for output column col (0..87)
template <int COL>
__device__ __forceinline__ float res_of(const float* __restrict__ x) {
  if constexpr (COL < 36)
    return x[COL % 9];
  else
    return x[9 + (COL - 36) % 13];
}

// fold one lo=4 component K4: 4 path t-values -> 4 copies -> staging
template <int K4>
__device__ __forceinline__ void fold4(float* __restrict__ pool, int tid,
                                      const float* __restrict__ x,
                                      const float* __restrict__ y,
                                      const float* __restrict__ w4) {
  const float t0 = tp_k<4, 4, 4, K4>(x, y);
  const float t1 = tp_k<4, 6, 4, K4>(x, y + 9);
  const float t2 = tp_k<6, 4, 4, K4>(x + 9, y);
  const float t3 = tp_k<6, 6, 4, K4>(x + 9, y + 9);
#pragma unroll
  for (int c = 0; c < 4; ++c) {
    float v = w4[c * 4 + 0] * t0 + w4[c * 4 + 1] * t1 + w4[c * 4 + 2] * t2 +
              w4[c * 4 + 3] * t3;
    if (c == 0) v += res_of<K4 + 0 * 22>(x);
    if (c == 1) v += res_of<K4 + 1 * 22>(x);
    if (c == 2) v += res_of<K4 + 2 * 22>(x);
    if (c == 3) v += res_of<K4 + 3 * 22>(x);
    pool[(c * 22 + K4) * SSTR + tid] = v;
  }
}

// fold one lo=6 component K6
template <int K6>
__device__ __forceinline__ void fold6(float* __restrict__ pool, int tid,
                                      const float* __restrict__ x,
                                      const float* __restrict__ y,
                                      const float* __restrict__ w6) {
  const float s0 = tp_k<4, 4, 6, K6>(x, y);
  const float s1 = tp_k<4, 6, 6, K6>(x, y + 9);
  const float s2 = tp_k<6, 4, 6, K6>(x + 9, y);
  const float s3 = tp_k<6, 6, 6, K6>(x + 9, y + 9);
#pragma unroll
  for (int c = 0; c < 4; ++c) {
    float v = w6[c * 4 + 0] * s0 + w6[c * 4 + 1] * s1 + w6[c * 4 + 2] * s2 +
              w6[c * 4 + 3] * s3;
    if (c == 0) v += res_of<9 + K6 + 0 * 22>(x);
    if (c == 1) v += res_of<9 + K6 + 1 * 22>(x);
    if (c == 2) v += res_of<9 + K6 + 2 * 22>(x);
    if (c == 3) v += res_of<9 + K6 + 3 * 22>(x);
    pool[(c * 22 + 9 + K6) * SSTR + tid] = v;
  }
}

// one |m| group: +m and -m of lo=4 and lo=6 share products -> one scope
template <int M>
__device__ __forceinline__ void emit_m(float* pool, int tid, const float* x,
                                       const float* y, const float* w4,
                                       const float* w6) {
  if constexpr (M <= 4) {
    fold4<4 + M>(pool, tid, x, y, w4);
    if constexpr (M > 0) fold4<4 - M>(pool, tid, x, y, w4);
  }
  fold6<6 + M>(pool, tid, x, y, w6);
  if constexpr (M > 0) fold6<6 - M>(pool, tid, x, y, w6);
}

template <int... Ms>
__device__ __forceinline__ void emit_all(float* pool, int tid, const float* x,
                                         const float* y, const float* w4,
                                         const float* w6,
                                         std::integer_sequence<int, Ms...>) {
  (emit_m<Ms>(pool, tid, x, y, w4, w6), ...);
}

// ============================================================================
// Main kernel (R15 body; phase A interior loads coalesced — layout unchanged)
// ============================================================================
__global__ __launch_bounds__(TILE, 4) void esc_kernel(
    const float* __restrict__ f4, const float* __restrict__ f6,
    const float* __restrict__ sw, const float* __restrict__ tw,
    float* __restrict__ out, int H, int W) {
  __shared__ float pool[POOLN];

  const int tid = threadIdx.x;
  const int h = blockIdx.y;
  const int w0 = blockIdx.x * TILE;
  const bool valid = (w0 + tid) < W;

  // ---- phase A: halo copy into packed [row][px][ch] planes
  const int gh0 = h - 1 < 0 ? 0 : h - 1;
  const int gh2 = h + 1 >= H ? H - 1 : h + 1;
  if ((w0 - 1 >= 0) && (w0 - 1 + NPX <= W)) {
    // interior in x: each tile plane is a CONTIGUOUS global span -> flat
    // coalesced copy (1 L1 wavefront per access instead of 9)
    const long b0 = (long)gh0 * W + (w0 - 1);
    const long b1 = (long)h * W + (w0 - 1);
    const long b2 = (long)gh2 * W + (w0 - 1);
    const float* r4[3] = {f4 + b0 * 9, f4 + b1 * 9, f4 + b2 * 9};
    const float* r6[3] = {f6 + b0 * 13, f6 + b1 * 13, f6 + b2 * 13};
#pragma unroll
    for (int r = 0; r < 3; ++r) {
      float* d4 = pool + r * (NPX * 9);
      for (int i = tid; i < NPX * 9; i += TILE) d4[i] = __ldg(r4[r] + i);
      float* d6 = pool + F6OFF + r * (NPX * 13);
      for (int i = tid; i < NPX * 13; i += TILE) d6[i] = __ldg(r6[r] + i);
    }
  } else {
    // boundary in x: clamped per-pixel copy (R15 path)
    for (int px = tid; px < NPX; px += TILE) {
      int gw = w0 - 1 + px;
      gw = gw < 0 ? 0 : (gw >= W ? W - 1 : gw);
#pragma unroll
      for (int r = 0; r < 3; ++r) {
        int gh = h - 1 + r;
        gh = gh < 0 ? 0 : (gh >= H ? H - 1 : gh);
        const long nn = (long)gh * W + gw;
        const float* s4 = f4 + nn * 9;
        float* d4 = pool + r * (NPX * 9) + px * 9;
#pragma unroll
        for (int c = 0; c < 9; ++c) d4[c] = __ldg(s4 + c);
        const float* s6 = f6 + nn * 13;
        float* d6 = pool + F6OFF + r * (NPX * 13) + px * 13;
#pragma unroll
        for (int c = 0; c < 13; ++c) d6[c] = __ldg(s6 + c);
      }
    }
  }
  __syncthreads();

  // ---- phase B1: depthwise 3x3 conv -> x[22], y[22]
  float x[22], y[22];
  if (valid) {
    float s9[9];
#pragma unroll
    for (int i = 0; i < 9; ++i) s9[i] = __ldg(sw + i);
#pragma unroll
    for (int ch = 0; ch < 9; ++ch) {
      float a = 0.f;
#pragma unroll
      for (int dr = 0; dr < 3; ++dr)
#pragma unroll
        for (int dc = 0; dc < 3; ++dc)
          a += s9[dr * 3 + dc] * pool[dr * (NPX * 9) + (tid + dc) * 9 + ch];
      y[ch] = a;
      x[ch] = pool[1 * (NPX * 9) + (tid + 1) * 9 + ch];
    }
#pragma unroll
    for (int ch = 0; ch < 13; ++ch) {
      float a = 0.f;
#pragma unroll
      for (int dr = 0; dr < 3; ++dr)
#pragma unroll
        for (int dc = 0; dc < 3; ++dc)
          a += s9[dr * 3 + dc] *
               pool[F6OFF + dr * (NPX * 13) + (tid + dc) * 13 + ch];
      y[9 + ch] = a;
      x[9 + ch] = pool[F6OFF + 1 * (NPX * 13) + (tid + 1) * 13 + ch];
    }
  }
  __syncthreads();  // conv tiles dead; pool becomes staging

  // ---- phase B2: streamed tensor products, grouped by |m|
  if (valid) {
    const float A4 = 1.5f;                 // sqrt(9/4)
    const float A6 = 1.8027756377319946f;  // sqrt(13/4)
    float w4[16], w6[16];
#pragma unroll
    for (int c = 0; c < 4; ++c)
#pragma unroll
      for (int p = 0; p < 4; ++p) {
        w4[c * 4 + p] = A4 * __ldg(tw + c * 8 + p);
        w6[c * 4 + p] = A6 * __ldg(tw + c * 8 + 4 + p);
      }

    emit_all(pool, tid, x, y, w4, w6, std::make_integer_sequence<int, 7>{});
  }
  __syncthreads();

  // ---- phase C: cooperative coalesced float4 stores
  const long rowbase = (long)h * W;
#pragma unroll
  for (int it = 0; it < 9; ++it) {
    int e = it * TILE + tid;
    int px = e / 9;
    int g = e - px * 9;
    int wp = w0 + px;
    if (wp < W) {
      int s = g * 4;
      float4 v =
          make_float4(pool[(s + 0) * SSTR + px], pool[(s + 1) * SSTR + px],
                      pool[(s + 2) * SSTR + px], pool[(s + 3) * SSTR + px]);
      *reinterpret_cast<float4*>(out + (rowbase + wp) * 36 + s) = v;
    }
  }
  float* out2 = out + (long)H * W * 36;
#pragma unroll
  for (int it = 0; it < 13; ++it) {
    int e = it * TILE + tid;
    int px = e / 13;
    int g = e - px * 13;
    int wp = w0 + px;
    if (wp < W) {
      int s = 36 + g * 4;
      float4 v =
          make_float4(pool[(s + 0) * SSTR + px], pool[(s + 1) * SSTR + px],
                      pool[(s + 2) * SSTR + px], pool[(s + 3) * SSTR + px]);
      *reinterpret_cast<float4*>(out2 + (rowbase + wp) * 52 + g * 4) = v;
    }
  }
}

// ============================================================================
extern "C" void kernel_launch(void* const* d_in, const int* in_sizes, int n_in,
                              void* d_out, int out_size) {
  (void)n_in;
  (void)out_size;
  const float* f4 = (const float*)d_in[0];
  const float* f6 = (const float*)d_in[1];
  const float* sw = (const float*)d_in[2];
  const float* tw = (const float*)d_in[3];
  float* out = (float*)d_out;

  const long n = (long)in_sizes[0] / 9;  // HW
  int W = (int)(sqrt((double)n) + 0.5);  // H = W = 768 here
  if (W < 1) W = 1;
  int H = (int)(n / W);

  dim3 grid((W + TILE - 1) / TILE, H);
  esc_kernel<<<grid, TILE>>>(f4, f6, sw, tw, out, H, W);
}